// round 3
// baseline (speedup 1.0000x reference)
#include <cuda_runtime.h>
#include <math.h>

#define BB 32
#define TT 1024
#define DD 768
#define HH 1024
#define BT (BB*TT)

// ---------------- scratch (device globals; no allocations) ----------------
__device__ float d_xln[(size_t)BT * DD];     // LN'd compacted tokens  (~100MB)
__device__ float d_part[8][BT];              // per-N-tile score partials
__device__ int   d_validx[BT];               // compacted row -> (b*T+t)
__device__ int   d_rowof[BT];                // (b*T+t) -> compacted row (or -1)
__device__ int   d_nv;                       // number of valid tokens
__device__ float d_Teff[BB];
__device__ float d_gall[3][BT];              // g_soft per rho
__device__ float d_keff[3][BB];
__device__ float d_poolacc[4][BB][DD];       // [full, rho0, rho1, rho2]

// out layout (floats):
//  g_soft [B,T]        @ 0
//  hard   [3,B,T]      @ 32768
//  recon_avg           @ 131072
//  losses [3]          @ 131073
//  rho_effs [3,B]      @ 131076
#define OFF_HARD  32768
#define OFF_RECON 131072
#define OFF_LOSS  131073
#define OFF_RHOE  131076

// ---------------- helpers ----------------
__device__ __forceinline__ float bsum1024(float v, float* red) {
    int t = threadIdx.x;
    red[t] = v; __syncthreads();
    #pragma unroll
    for (int o = 512; o > 0; o >>= 1) {
        if (t < o) red[t] += red[t + o];
        __syncthreads();
    }
    float r = red[0]; __syncthreads();
    return r;
}

// ---------------- 1) compact valid tokens + zero accumulators ----------------
__global__ void k_compact(const int* __restrict__ attn) {
    int t = threadIdx.x, lane = t & 31, w = t >> 5;
    __shared__ int wTot[32], wOff[32];
    __shared__ int sBase, sCnt;
    if (t == 0) sBase = 0;
    __syncthreads();
    for (int b = 0; b < BB; b++) {
        int idx = b * TT + t;
        int flag = (attn[idx] != 0);
        unsigned m = __ballot_sync(0xffffffffu, flag);
        int pin = __popc(m & ((1u << lane) - 1u));
        if (lane == 0) wTot[w] = __popc(m);
        __syncthreads();
        if (t < 32) {
            int v = wTot[t], x = v;
            #pragma unroll
            for (int o = 1; o < 32; o <<= 1) {
                int y = __shfl_up_sync(0xffffffffu, x, o);
                if (lane >= o) x += y;
            }
            wOff[t] = x - v;
            if (t == 31) sCnt = x;
        }
        __syncthreads();
        int p = sBase + wOff[w] + pin;
        if (flag) { d_validx[p] = idx; d_rowof[idx] = p; }
        else      { d_rowof[idx] = -1; }
        __syncthreads();
        if (t == 0) { d_Teff[b] = (float)sCnt; sBase += sCnt; }
        __syncthreads();
    }
    if (t == 0) d_nv = sBase;
    float* pa = (float*)d_poolacc;
    for (int i = t; i < 4 * BB * DD; i += 1024) pa[i] = 0.f;
}

// ---------------- 2) LayerNorm of valid tokens (compacted, float4 I/O) -------
// 192 threads; reduction folds 192 -> 64 explicitly, then power-of-2 tree.
__global__ __launch_bounds__(192) void k_ln(const float* __restrict__ emb,
                                            const float* __restrict__ g,
                                            const float* __restrict__ bb) {
    int r = blockIdx.x;
    if (r >= d_nv) return;
    int tok = d_validx[r];
    const float4* x4 = (const float4*)(emb + (size_t)tok * DD);
    int t = threadIdx.x;                  // 0..191 ; DD/4 = 192 float4
    float4 v = x4[t];
    __shared__ float red[192];

    red[t] = v.x + v.y + v.z + v.w; __syncthreads();
    if (t < 64) red[t] += red[t + 64] + red[t + 128];
    __syncthreads();
    #pragma unroll
    for (int o = 32; o > 0; o >>= 1) { if (t < o) red[t] += red[t + o]; __syncthreads(); }
    float mu = red[0] * (1.0f / (float)DD);
    __syncthreads();

    float ex = v.x - mu, ey = v.y - mu, ez = v.z - mu, ew = v.w - mu;
    red[t] = ex * ex + ey * ey + ez * ez + ew * ew; __syncthreads();
    if (t < 64) red[t] += red[t + 64] + red[t + 128];
    __syncthreads();
    #pragma unroll
    for (int o = 32; o > 0; o >>= 1) { if (t < o) red[t] += red[t + o]; __syncthreads(); }
    float inv = rsqrtf(red[0] * (1.0f / (float)DD) + 1e-5f);

    float4 gv = ((const float4*)g)[t];
    float4 bv = ((const float4*)bb)[t];
    float4 o;
    o.x = ex * inv * gv.x + bv.x;
    o.y = ey * inv * gv.y + bv.y;
    o.z = ez * inv * gv.z + bv.z;
    o.w = ew * inv * gv.w + bv.w;
    ((float4*)(d_xln + (size_t)r * DD))[t] = o;
}

// ---------------- 3) fused GEMM + bias + exact GELU + w2-reduce ----------------
// scores_partial[nblk][row] = sum_{n in tile} gelu(xln@w1 + b1)[row,n] * w2[n]
__global__ __launch_bounds__(256) void k_gemm(const float* __restrict__ w1,
                                              const float* __restrict__ b1,
                                              const float* __restrict__ w2) {
    int nv = d_nv;
    int row0 = blockIdx.x * 128;
    if (row0 >= nv) return;
    int n0 = blockIdx.y * 128;

    __shared__ float As[16][128];
    __shared__ float Bs[16][128];

    int tid = threadIdx.x;
    int tx = tid & 15, ty = tid >> 4;

    float acc[8][8];
    #pragma unroll
    for (int i = 0; i < 8; i++)
        #pragma unroll
        for (int j = 0; j < 8; j++) acc[i][j] = 0.f;

    int aRow = tid >> 1;      // 0..127
    int aQ   = tid & 1;       // quads aQ, aQ+2
    int bK   = tid >> 5;      // k rows bK, bK+8
    int bQ   = tid & 31;      // float4 col

    const float4* A4 = (const float4*)d_xln;
    const float4* B4 = (const float4*)w1;
    bool aValid = (row0 + aRow) < nv;
    size_t aBase = (size_t)(row0 + aRow) * (DD / 4);

    for (int k0 = 0; k0 < DD; k0 += 16) {
        float4 va0 = aValid ? A4[aBase + (k0 >> 2) + aQ]     : make_float4(0, 0, 0, 0);
        float4 va1 = aValid ? A4[aBase + (k0 >> 2) + aQ + 2] : make_float4(0, 0, 0, 0);
        float4 vb0 = B4[(size_t)(k0 + bK)     * (HH / 4) + (n0 >> 2) + bQ];
        float4 vb1 = B4[(size_t)(k0 + bK + 8) * (HH / 4) + (n0 >> 2) + bQ];
        __syncthreads();
        As[aQ * 4 + 0][aRow] = va0.x; As[aQ * 4 + 1][aRow] = va0.y;
        As[aQ * 4 + 2][aRow] = va0.z; As[aQ * 4 + 3][aRow] = va0.w;
        As[(aQ + 2) * 4 + 0][aRow] = va1.x; As[(aQ + 2) * 4 + 1][aRow] = va1.y;
        As[(aQ + 2) * 4 + 2][aRow] = va1.z; As[(aQ + 2) * 4 + 3][aRow] = va1.w;
        ((float4*)(&Bs[bK][0]))[bQ] = vb0;
        ((float4*)(&Bs[bK + 8][0]))[bQ] = vb1;
        __syncthreads();
        #pragma unroll
        for (int kk = 0; kk < 16; kk++) {
            float aR[8], bR[8];
            #pragma unroll
            for (int i = 0; i < 8; i++) aR[i] = As[kk][ty * 8 + i];
            #pragma unroll
            for (int j = 0; j < 8; j++) bR[j] = Bs[kk][tx * 8 + j];
            #pragma unroll
            for (int i = 0; i < 8; i++)
                #pragma unroll
                for (int j = 0; j < 8; j++)
                    acc[i][j] += aR[i] * bR[j];
        }
    }
    __syncthreads();

    float b1c[8], w2c[8];
    #pragma unroll
    for (int j = 0; j < 8; j++) {
        b1c[j] = b1[n0 + tx * 8 + j];
        w2c[j] = w2[n0 + tx * 8 + j];
    }
    float* rbuf = &As[0][0];  // 2048 floats
    #pragma unroll
    for (int i = 0; i < 8; i++) {
        float p = 0.f;
        #pragma unroll
        for (int j = 0; j < 8; j++) {
            float h = acc[i][j] + b1c[j];
            float ge = 0.5f * h * (1.0f + erff(h * 0.70710678118654752440f));
            p += ge * w2c[j];
        }
        rbuf[(ty * 8 + i) * 16 + tx] = p;
    }
    __syncthreads();
    if (tid < 128) {
        int row = row0 + tid;
        if (row < nv) {
            float s = 0.f;
            #pragma unroll
            for (int q = 0; q < 16; q++) s += rbuf[tid * 16 + q];
            d_part[blockIdx.y][row] = s;  // fixed-order, no atomics: deterministic
        }
    }
}

// ---------------- 4) soft-rank + gates + hard masks ----------------
__global__ __launch_bounds__(1024) void k_rank(const int* __restrict__ attn,
                                               const float* __restrict__ b2,
                                               float* __restrict__ out) {
    int b = blockIdx.x, j = threadIdx.x;
    __shared__ float sn[1024];
    __shared__ float rk[1024];
    __shared__ float red[1024];

    int idx = b * TT + j;
    float a = (attn[idx] != 0) ? 1.f : 0.f;
    float sraw = 0.f;
    if (a > 0.f) {
        int row = d_rowof[idx];
        float s = 0.f;
        #pragma unroll
        for (int n = 0; n < 8; n++) s += d_part[n][row];
        sraw = s + b2[0];
    }
    float Teff = d_Teff[b];
    float denom = fmaxf(Teff, 1.0f);
    float S1 = bsum1024(sraw, red);
    float mean = S1 / denom;
    float dv = sraw - mean;
    float S2 = bsum1024(dv * dv * a, red);
    float var = S2 / denom;
    float snorm = (sraw - mean) / sqrtf(var + 1e-6f);
    sn[j] = snorm;
    __syncthreads();

    float r;
    if (a > 0.f) {
        float a0 = 0.f, a1 = 0.f, a2 = 0.f, a3 = 0.f;
        float sj = snorm;
        for (int i = 0; i < 1024; i += 4) {
            float d0 = (sj - sn[i])     * 20.0f; float s0 = 1.f / (1.f + __expf(-d0)); a0 += s0 * s0;
            float d1 = (sj - sn[i + 1]) * 20.0f; float s1 = 1.f / (1.f + __expf(-d1)); a1 += s1 * s1;
            float d2 = (sj - sn[i + 2]) * 20.0f; float s2 = 1.f / (1.f + __expf(-d2)); a2 += s2 * s2;
            float d3 = (sj - sn[i + 3]) * 20.0f; float s3 = 1.f / (1.f + __expf(-d3)); a3 += s3 * s3;
        }
        r = 1.f + ((a0 + a1) + (a2 + a3));
    } else {
        r = 1e9f;
    }
    rk[j] = r;
    __syncthreads();

    int pos = 0;
    for (int i = 0; i < 1024; i++) {
        float ri = rk[i];
        pos += (ri < r) || (ri == r && i < j);
    }
    float fpos = (float)pos;

    const float rhos[3] = {0.1f, 0.25f, 0.5f};
    #pragma unroll
    for (int q = 0; q < 3; q++) {
        float k = fmaxf(rintf(rhos[q] * Teff), 1.0f);
        float gate = (a > 0.f) ? 1.f / (1.f + __expf(-(k - r) * 5.0f)) : 0.f;
        float Sg = bsum1024(gate, red);
        float g = gate / fmaxf(Sg, 1e-8f) * k;
        d_gall[q][idx] = g;
        if (q == 2) out[idx] = g;                    // g_soft output = last rho
        out[OFF_HARD + q * BT + idx] = (fpos < k) ? 1.f : 0.f;
        float Sg2 = bsum1024(g, red);
        if (j == 0) {
            d_keff[q][b] = Sg2;
            out[OFF_RHOE + q * BB + b] = Sg2 / fmaxf(Teff, 1.0f);
        }
    }
}

// ---------------- 5) pooled representations (all 4 weightings in one pass) ----
__global__ __launch_bounds__(256) void k_pool(const int* __restrict__ ids,
                                              const int* __restrict__ attn,
                                              const float* __restrict__ etab) {
    int b = blockIdx.x;
    int t0 = blockIdx.y * 128;
    int tid = threadIdx.x;
    float accF[3] = {0, 0, 0}, ac0[3] = {0, 0, 0}, ac1[3] = {0, 0, 0}, ac2[3] = {0, 0, 0};
    for (int t = t0; t < t0 + 128; t++) {
        int idx = b * TT + t;
        if (attn[idx] == 0) continue;
        int id = ids[idx];
        float w0 = d_gall[0][idx], w1v = d_gall[1][idx], w2v = d_gall[2][idx];
        const float* row = etab + (size_t)id * DD;
        #pragma unroll
        for (int i = 0; i < 3; i++) {
            float v = __ldg(row + tid + 256 * i);
            accF[i] += v; ac0[i] += v * w0; ac1[i] += v * w1v; ac2[i] += v * w2v;
        }
    }
    #pragma unroll
    for (int i = 0; i < 3; i++) {
        int d = tid + 256 * i;
        atomicAdd(&d_poolacc[0][b][d], accF[i]);
        atomicAdd(&d_poolacc[1][b][d], ac0[i]);
        atomicAdd(&d_poolacc[2][b][d], ac1[i]);
        atomicAdd(&d_poolacc[3][b][d], ac2[i]);
    }
}

// ---------------- 6) losses ----------------
__global__ __launch_bounds__(1024) void k_final(float* __restrict__ out) {
    int t = threadIdx.x;
    __shared__ float red[1024];
    __shared__ float sl[3];
    for (int q = 0; q < 3; q++) {
        float s = 0.f;
        for (int n = t; n < BB * DD; n += 1024) {
            int b = n / DD, d = n % DD;
            float Te = d_Teff[b];
            float full = d_poolacc[0][b][d] / fmaxf(Te, 1e-9f);
            float pred = d_poolacc[1 + q][b][d] / fmaxf(d_keff[q][b], 1e-9f);
            float df = pred - full;
            s += df * df;
        }
        float S = bsum1024(s, red);
        if (t == 0) sl[q] = S / (float)(BB * DD);
        __syncthreads();
    }
    if (t == 0) {
        float l0 = sl[0], l1 = sl[1], l2 = sl[2];
        float recon = ((l0 + l1) + l2) / 3.0f;
        out[OFF_RECON] = recon;
        out[OFF_LOSS + 0] = l0;
        out[OFF_LOSS + 1] = l1;
        out[OFF_LOSS + 2] = l2;
    }
}

// ---------------- launch ----------------
extern "C" void kernel_launch(void* const* d_in, const int* in_sizes, int n_in,
                              void* d_out, int out_size) {
    const int*   ids  = (const int*)d_in[0];
    const float* emb  = (const float*)d_in[1];
    const int*   attn = (const int*)d_in[2];
    const float* ln_g = (const float*)d_in[3];
    const float* ln_b = (const float*)d_in[4];
    const float* w1   = (const float*)d_in[5];
    const float* b1   = (const float*)d_in[6];
    const float* w2   = (const float*)d_in[7];
    const float* b2   = (const float*)d_in[8];
    const float* etab = (const float*)d_in[9];
    float* out = (float*)d_out;

    k_compact<<<1, 1024>>>(attn);
    k_ln<<<BT, 192>>>(emb, ln_g, ln_b);
    dim3 gg(BT / 128, HH / 128);
    k_gemm<<<gg, 256>>>(w1, b1, w2);
    k_rank<<<BB, 1024>>>(attn, b2, out);
    dim3 gp(BB, TT / 128);
    k_pool<<<gp, 256>>>(ids, attn, etab);
    k_final<<<1, 1024>>>(out);
}